// round 16
// baseline (speedup 1.0000x reference)
#include <cuda_runtime.h>
#include <cuda_fp16.h>
#include <cstdint>
#include <cstddef>

// Problem constants
#define B_ 8
#define T_ 2048
#define C_ 1024
#define BT_ (B_ * T_)        // 16384
#define C3_ (3 * C_)         // 3072
#define C4_ (4 * C_)         // 4096

// ---------------- scratch (static device globals; no allocation) ----------------
__device__ float  g_x1[(size_t)BT_ * C_];    // x after time mixing
__device__ float  g_kvr[(size_t)BT_ * C3_];  // raw kvr from GEMM1 (fp32)
__device__ __half g_xnh[(size_t)BT_ * C_];   // LN output (fp16), xn1 then xn2
__device__ __half g_hh[(size_t)BT_ * C4_];   // channel-mix hidden (fp16, post relu^2)
__device__ __half g_wtm[(size_t)C3_ * C_];   // W_tm^T fp16  [3C][C]
__device__ __half g_wcm[(size_t)C4_ * C_];   // W_cm^T fp16  [4C][C]
__device__ __half g_wcp[(size_t)C_ * C4_];   // W_cp^T fp16  [C][4C]

// =================== small helpers ===================
__device__ __forceinline__ uint32_t smem_u32(const void* p) {
    uint32_t a;
    asm("{ .reg .u64 t; cvta.to.shared.u64 t, %1; cvt.u32.u64 %0, t; }" : "=r"(a) : "l"(p));
    return a;
}
__device__ __forceinline__ void cp16(uint32_t s, const void* g) {
    asm volatile("cp.async.cg.shared.global [%0], [%1], 16;" :: "r"(s), "l"(g));
}
#define CP_COMMIT() asm volatile("cp.async.commit_group;" ::: "memory")
#define CP_WAIT1()  asm volatile("cp.async.wait_group 1;" ::: "memory")
#define CP_WAIT3()  asm volatile("cp.async.wait_group 3;" ::: "memory")

__device__ __forceinline__ void ldsm4(uint32_t* r, uint32_t addr) {
    asm volatile("ldmatrix.sync.aligned.m8n8.x4.shared.b16 {%0,%1,%2,%3}, [%4];"
                 : "=r"(r[0]), "=r"(r[1]), "=r"(r[2]), "=r"(r[3]) : "r"(addr));
}
__device__ __forceinline__ void mma_f16(float* c, const uint32_t* a, const uint32_t* b) {
    asm volatile(
        "mma.sync.aligned.m16n8k16.row.col.f32.f16.f16.f32 "
        "{%0,%1,%2,%3}, {%4,%5,%6,%7}, {%8,%9}, {%0,%1,%2,%3};\n"
        : "+f"(c[0]), "+f"(c[1]), "+f"(c[2]), "+f"(c[3])
        : "r"(a[0]), "r"(a[1]), "r"(a[2]), "r"(a[3]), "r"(b[0]), "r"(b[1]));
}
__device__ __forceinline__ float sigmoidf_(float z) {
    return 1.0f / (1.0f + __expf(-z));
}

// =================== fp16 tensor GEMM: 3-stage cp.async, 2 CTAs/SM ====================
// C[M,N] = A[M,K] @ B[K,N]; A fp16 [M][K] row-major, Bt fp16 [N][K] (pre-transposed).
// CTA tile MT x 128 (MT = 128 or 64), BK=32, 256 threads.
#define ROWB 80

// EPI: 0 = plain fp32 store (kvr); 1 = channel-mix relu^2 -> fp16; 2 = final residual fp32
template <int EPI>
__device__ __forceinline__ void epi2(void* __restrict__ Cout, int N, int row, int col,
                                     float v0, float v1,
                                     const float* __restrict__ x1p,
                                     const float* __restrict__ gate,
                                     const __half* __restrict__ xn2) {
    if (EPI == 0) {
        *(float2*)&((float*)Cout)[(size_t)row * N + col] = make_float2(v0, v1);
    } else if (EPI == 1) {
        int t = row & (T_ - 1);
        int rp = row - t + ((t > 0) ? t - 1 : T_ - 1);
        int c0 = col & (C_ - 1), c1 = (col + 1) & (C_ - 1);
        float xp0 = x1p[(size_t)rp * C_ + c0];
        float xp1 = x1p[(size_t)rp * C_ + c1];
        float k0 = fmaxf((v0 - xp0) * gate[c0] + xp0, 0.f);
        float k1 = fmaxf((v1 - xp1) * gate[c1] + xp1, 0.f);
        *(__half2*)&((__half*)Cout)[(size_t)row * N + col] = __floats2half2_rn(k0 * k0, k1 * k1);
    } else {
        int t = row & (T_ - 1);
        int rp = row - t + ((t > 0) ? t - 1 : T_ - 1);
        float xp0 = x1p[(size_t)rp * C_ + col];
        float xp1 = x1p[(size_t)rp * C_ + col + 1];
        size_t o = (size_t)row * C_ + col;
        float r0 = sigmoidf_((__half2float(xn2[o])     - xp0) * gate[col]     + xp0);
        float r1 = sigmoidf_((__half2float(xn2[o + 1]) - xp1) * gate[col + 1] + xp1);
        *(float2*)&((float*)Cout)[o] = make_float2(x1p[o] + r0 * v0, x1p[o + 1] + r1 * v1);
    }
}

template <int EPI, int MT>
__global__ __launch_bounds__(256, 2)
void gemm_f16(const __half* __restrict__ A, const __half* __restrict__ Bt,
              void* __restrict__ Cout, int M, int N, int K,
              const float* __restrict__ e_x1, const float* __restrict__ e_gate,
              const __half* __restrict__ e_xn2) {
    constexpr int NWM  = MT / 32;          // m-warps (4 or 2)
    constexpr int WNW  = 16 * NWM;         // warp n-width (64 or 32)
    constexpr int NJJ  = WNW / 16;         // 16-col ldmatrix blocks per warp (4 or 2)
    constexpr int NACC = WNW / 8;          // 8-col acc blocks per warp (8 or 4)
    constexpr uint32_t TILEA = (uint32_t)MT * ROWB;
    constexpr uint32_t STAGE = TILEA + 128u * ROWB;

    extern __shared__ char dsm[];
    const uint32_t su = smem_u32(dsm);

    const int tid = threadIdx.x;
    const int lane = tid & 31;
    const int wid = tid >> 5;
    const int wm = (wid % NWM) * 32;
    const int wn = (wid / NWM) * WNW;
    const int g = lane >> 2;
    const int tig = lane & 3;

    const int m0 = blockIdx.y * MT;
    const int n0 = blockIdx.x * 128;

    const int prow = tid >> 2;             // 0..63
    const int pseg = tid & 3;
    const __half* Ap0 = A + (size_t)(m0 + prow) * K + pseg * 8;
    const __half* Ap1 = A + (size_t)(m0 + prow + 64) * K + pseg * 8;   // MT==128 only
    const __half* Bp0 = Bt + (size_t)(n0 + prow) * K + pseg * 8;
    const __half* Bp1 = Bt + (size_t)(n0 + prow + 64) * K + pseg * 8;
    const uint32_t soA0 = (uint32_t)(prow * ROWB + pseg * 16);
    const uint32_t soA1 = (uint32_t)((prow + 64) * ROWB + pseg * 16);
    const uint32_t soB0 = TILEA + soA0;
    const uint32_t soB1 = TILEA + (uint32_t)((prow + 64) * ROWB + pseg * 16);

    const int ntiles = K >> 5;

    // prologue: stages 0, 1
#pragma unroll
    for (int s = 0; s < 2; s++) {
        uint32_t sb0 = su + s * STAGE;
        size_t koff = (size_t)s * 32;
        cp16(sb0 + soA0, Ap0 + koff);
        if (MT == 128) cp16(sb0 + soA1, Ap1 + koff);
        cp16(sb0 + soB0, Bp0 + koff);
        cp16(sb0 + soB1, Bp1 + koff);
        CP_COMMIT();
    }

    float acc[2][NACC][4];
#pragma unroll
    for (int i = 0; i < 2; i++)
#pragma unroll
        for (int j = 0; j < NACC; j++)
#pragma unroll
            for (int v = 0; v < 4; v++) acc[i][j][v] = 0.f;

    const uint32_t aro = (uint32_t)(lane & 15) * ROWB + (uint32_t)(lane >> 4) * 16;
    const uint32_t bro = (uint32_t)((lane & 7) + ((lane >> 4) << 3)) * ROWB
                       + (uint32_t)((lane >> 3) & 1) * 16;

    int cur = 0, nxt = 2;
    for (int kt = 0; kt < ntiles; kt++) {
        CP_WAIT1();
        __syncthreads();

        if (kt + 2 < ntiles) {
            uint32_t sb0 = su + nxt * STAGE;
            size_t koff = (size_t)(kt + 2) * 32;
            cp16(sb0 + soA0, Ap0 + koff);
            if (MT == 128) cp16(sb0 + soA1, Ap1 + koff);
            cp16(sb0 + soB0, Bp0 + koff);
            cp16(sb0 + soB1, Bp1 + koff);
        }
        CP_COMMIT();

        const uint32_t st = su + cur * STAGE;
#pragma unroll
        for (int ks = 0; ks < 2; ks++) {
            uint32_t a[2][4];
#pragma unroll
            for (int i = 0; i < 2; i++)
                ldsm4(a[i], st + (uint32_t)(wm + i * 16) * ROWB + ks * 32 + aro);
#pragma unroll
            for (int jj = 0; jj < NJJ; jj++) {
                uint32_t bfr[4];
                ldsm4(bfr, st + TILEA + (uint32_t)(wn + jj * 16) * ROWB + ks * 32 + bro);
#pragma unroll
                for (int i = 0; i < 2; i++) {
                    mma_f16(acc[i][2 * jj],     a[i], bfr + 0);
                    mma_f16(acc[i][2 * jj + 1], a[i], bfr + 2);
                }
            }
        }
        __syncthreads();
        cur = (cur == 2) ? 0 : cur + 1;
        nxt = (nxt == 2) ? 0 : nxt + 1;
    }

#pragma unroll
    for (int i = 0; i < 2; i++) {
        const int row = m0 + wm + i * 16 + g;
#pragma unroll
        for (int j = 0; j < NACC; j++) {
            const int col = n0 + wn + j * 8 + 2 * tig;
            epi2<EPI>(Cout, N, row,     col, acc[i][j][0], acc[i][j][1], e_x1, e_gate, e_xn2);
            epi2<EPI>(Cout, N, row + 8, col, acc[i][j][2], acc[i][j][3], e_x1, e_gate, e_xn2);
        }
    }
}

#define SMEMB_128 (3 * (128 + 128) * ROWB)   // 61440
#define SMEMB_64  (3 * (64 + 128) * ROWB)    // 46080

// =================== weight convert + transpose: fp32 [K][N] -> fp16 [N][K] ===========
__global__ void wconv(const float* __restrict__ in, __half* __restrict__ out, int K, int N) {
    __shared__ float t[32][33];
    int n0 = blockIdx.x * 32, k0 = blockIdx.y * 32;
    int tx = threadIdx.x, ty = threadIdx.y;  // 32x8
#pragma unroll
    for (int q = 0; q < 4; q++)
        t[ty + q * 8][tx] = in[(size_t)(k0 + ty + q * 8) * N + n0 + tx];
    __syncthreads();
#pragma unroll
    for (int q = 0; q < 4; q++)
        out[(size_t)(n0 + ty + q * 8) * K + k0 + tx] = __float2half_rn(t[tx][ty + q * 8]);
}

// =================== LayerNorm -> fp16 ===================
__global__ void ln_kernel_h(const float* __restrict__ x,
                            const float* __restrict__ g,
                            const float* __restrict__ b,
                            __half* __restrict__ out) {
    size_t row = blockIdx.x;
    int tid = threadIdx.x;
    const float4* xr = reinterpret_cast<const float4*>(x + row * C_);
    float4 v = xr[tid];
    float s = v.x + v.y + v.z + v.w;
    float s2 = v.x * v.x + v.y * v.y + v.z * v.z + v.w * v.w;

    __shared__ float sa[8], sb[8];
    for (int o = 16; o > 0; o >>= 1) {
        s  += __shfl_down_sync(0xffffffffu, s, o);
        s2 += __shfl_down_sync(0xffffffffu, s2, o);
    }
    int w = tid >> 5, l = tid & 31;
    if (l == 0) { sa[w] = s; sb[w] = s2; }
    __syncthreads();
    if (w == 0) {
        s  = (l < 8) ? sa[l] : 0.f;
        s2 = (l < 8) ? sb[l] : 0.f;
        for (int o = 4; o > 0; o >>= 1) {
            s  += __shfl_down_sync(0xffffffffu, s, o);
            s2 += __shfl_down_sync(0xffffffffu, s2, o);
        }
        if (l == 0) { sa[0] = s; sb[0] = s2; }
    }
    __syncthreads();
    float mean = sa[0] * (1.0f / C_);
    float var = sb[0] * (1.0f / C_) - mean * mean;
    float rstd = rsqrtf(var + 1e-5f);

    float4 gg = reinterpret_cast<const float4*>(g)[tid];
    float4 bb = reinterpret_cast<const float4*>(b)[tid];
    __half2 h0 = __floats2half2_rn((v.x - mean) * rstd * gg.x + bb.x,
                                   (v.y - mean) * rstd * gg.y + bb.y);
    __half2 h1 = __floats2half2_rn((v.z - mean) * rstd * gg.z + bb.z,
                                   (v.w - mean) * rstd * gg.w + bb.w);
    __half2* op = reinterpret_cast<__half2*>(out + row * C_);
    op[tid * 2]     = h0;
    op[tid * 2 + 1] = h1;
}

// =================== WKV v3: cp.async pipeline + exp-domain recurrence ===================
#define WKV_TD 8
#define WKV_S  5

__global__ __launch_bounds__(64)
void wkv_pipe(const float* __restrict__ kvr, const float* __restrict__ x,
              const float* __restrict__ tmk, const float* __restrict__ tmv,
              const float* __restrict__ tmr,
              const float* __restrict__ wd, const float* __restrict__ uf,
              float* __restrict__ x1, float* __restrict__ state_out) {
    __shared__ float stg[4 * WKV_S * WKV_TD * 64];
    const uint32_t su = smem_u32(stg);

    const int tid = threadIdx.x;
    const int b = blockIdx.x >> 4;
    const int cg = (blockIdx.x & 15) * 64;
    const int c = cg + tid;

    const int pten = tid >> 4;
    const int pseg = (tid & 15) * 4;
    const float* kbase = kvr + (size_t)b * T_ * C3_ + cg;
    const float* src_base;
    size_t tstride;
    if (pten == 0)      { src_base = kbase;            tstride = C3_; }
    else if (pten == 1) { src_base = kbase + C_;       tstride = C3_; }
    else if (pten == 2) { src_base = kbase + 2 * C_;   tstride = C3_; }
    else                { src_base = x + (size_t)b * T_ * C_ + cg; tstride = C_; }

    const uint32_t pbase = su + (uint32_t)pten * (WKV_S * WKV_TD * 256) + (uint32_t)pseg * 4;

    const float mk = tmk[c], mv = tmv[c], mr = tmr[c];
    const float w = wd[c], u = uf[c];
    float aa = 0.f;
    float P = -1e38f, S = 1.0f;      // bb = P + log(S)
    float* ob = x1 + (size_t)b * T_ * C_ + c;

    const int nst = T_ / WKV_TD;

#pragma unroll
    for (int s = 0; s < WKV_S - 1; s++) {
#pragma unroll
        for (int tt = 0; tt < WKV_TD; tt++) {
            cp16(pbase + (uint32_t)(s * WKV_TD + tt) * 256,
                 src_base + (size_t)(s * WKV_TD + tt) * tstride + pseg);
        }
        CP_COMMIT();
    }

    float xp = 0.f;
#pragma unroll 1
    for (int st = 0; st < nst; st++) {
        const int slot = st % WKV_S;
        CP_WAIT3();
        __syncthreads();

        const int stp = st + WKV_S - 1;
        if (stp < nst) {
            const int ps = stp % WKV_S;
#pragma unroll
            for (int tt = 0; tt < WKV_TD; tt++) {
                cp16(pbase + (uint32_t)(ps * WKV_TD + tt) * 256,
                     src_base + (size_t)(stp * WKV_TD + tt) * tstride + pseg);
            }
        }
        CP_COMMIT();

        float kr[WKV_TD], vr[WKV_TD], rr[WKV_TD], xr[WKV_TD];
        const float* sk = stg + (0 * WKV_S + slot) * (WKV_TD * 64);
        const float* sv = stg + (1 * WKV_S + slot) * (WKV_TD * 64);
        const float* sr = stg + (2 * WKV_S + slot) * (WKV_TD * 64);
        const float* sx = stg + (3 * WKV_S + slot) * (WKV_TD * 64);
#pragma unroll
        for (int tt = 0; tt < WKV_TD; tt++) {
            kr[tt] = sk[tt * 64 + tid];
            vr[tt] = sv[tt * 64 + tid];
            rr[tt] = sr[tt * 64 + tid];
            xr[tt] = sx[tt * 64 + tid];
        }
        if (st == 0) xp = xr[0];

#pragma unroll
        for (int tt = 0; tt < WKV_TD; tt++) {
            float km = (kr[tt] - xp) * mk + xp;
            float vm = (vr[tt] - xp) * mv + xp;
            float rm = (rr[tt] - xp) * mr + xp;
            float rsg = __fdividef(1.f, 1.f + __expf(-rm));
            float rcpS = __fdividef(1.f, S);
            float a2 = u + km - P;
            float g2  = __expf(a2);
            float g2i = __expf(-a2);
            bool  c2 = (S >= g2);
            float e1 = c2 ? 1.f : S * g2i;
            float e2 = c2 ? g2 * rcpS : 1.f;
            float y  = __fdividef(e1 * aa + e2 * vm, e1 + e2 + 1e-8f);
            ob[(size_t)(st * WKV_TD + tt) * C_] = xr[tt] + rsg * y;
            float a1 = km - w - P;
            float g1  = __expf(a1);
            float g1i = __expf(-a1);
            bool  c1 = (S >= g1);
            float f2  = c1 ? g1 * rcpS : 1.f;
            float f1s = c1 ? 1.f : S * g1i;
            aa = f1s * aa + f2 * vm;
            S  = c1 ? (S + g1) : (S * g1i + 1.f);
            P  = c1 ? (w + P) : km;
            xp = xr[tt];
        }
        P += __logf(S);
        S = 1.0f;
    }
    state_out[(size_t)(b * C_ + c) * 2]     = aa;
    state_out[(size_t)(b * C_ + c) * 2 + 1] = P;
}

// =================== host ===================
extern "C" void kernel_launch(void* const* d_in, const int* in_sizes, int n_in,
                              void* d_out, int out_size) {
    const float* x    = (const float*)d_in[0];
    const float* wdec = (const float*)d_in[1];
    const float* ufst = (const float*)d_in[2];
    const float* W_tm = (const float*)d_in[3];
    const float* g1   = (const float*)d_in[4];
    const float* b1   = (const float*)d_in[5];
    const float* tmk  = (const float*)d_in[6];
    const float* tmv  = (const float*)d_in[7];
    const float* tmr  = (const float*)d_in[8];
    const float* W_cm = (const float*)d_in[9];
    const float* W_cp = (const float*)d_in[10];
    const float* g2   = (const float*)d_in[11];
    const float* b2   = (const float*)d_in[12];
    const float* cmk  = (const float*)d_in[13];
    const float* cmr  = (const float*)d_in[14];
    float* out = (float*)d_out;

    float *x1, *kvr;
    __half *xnh, *hh, *wtm, *wcm, *wcp;
    cudaGetSymbolAddress((void**)&x1,  g_x1);
    cudaGetSymbolAddress((void**)&kvr, g_kvr);
    cudaGetSymbolAddress((void**)&xnh, g_xnh);
    cudaGetSymbolAddress((void**)&hh,  g_hh);
    cudaGetSymbolAddress((void**)&wtm, g_wtm);
    cudaGetSymbolAddress((void**)&wcm, g_wcm);
    cudaGetSymbolAddress((void**)&wcp, g_wcp);

    float* state_out = out + (size_t)BT_ * C_;

    cudaFuncSetAttribute(gemm_f16<0, 128>, cudaFuncAttributeMaxDynamicSharedMemorySize, SMEMB_128);
    cudaFuncSetAttribute(gemm_f16<1, 128>, cudaFuncAttributeMaxDynamicSharedMemorySize, SMEMB_128);
    cudaFuncSetAttribute(gemm_f16<2, 64>,  cudaFuncAttributeMaxDynamicSharedMemorySize, SMEMB_64);

    dim3 wcb(32, 8);
    // 0. weight convert + transpose to fp16 [N][K]  (serial, default stream)
    wconv<<<dim3(C3_ / 32, C_ / 32), wcb>>>(W_tm, wtm, C_, C3_);
    wconv<<<dim3(C4_ / 32, C_ / 32), wcb>>>(W_cm, wcm, C_, C4_);
    wconv<<<dim3(C_ / 32, C4_ / 32), wcb>>>(W_cp, wcp, C4_, C_);

    // 1. LayerNorm 1 -> fp16
    ln_kernel_h<<<BT_, 256>>>(x, g1, b1, xnh);
    // 2. GEMM1: kvr = xn1 @ W_tm   (M=16384, N=3072, K=1024), fp32 out
    gemm_f16<0, 128><<<dim3(C3_ / 128, BT_ / 128), 256, SMEMB_128>>>(
        xnh, wtm, kvr, BT_, C3_, C_, nullptr, nullptr, nullptr);
    // 3. WKV v3 -> x1, state
    wkv_pipe<<<128, 64>>>(kvr, x, tmk, tmv, tmr, wdec, ufst, x1, state_out);
    // 4. LayerNorm 2 -> fp16
    ln_kernel_h<<<BT_, 256>>>(x1, g2, b2, xnh);
    // 5. GEMM2: h = relu(mix(xn2 @ W_cm))^2 -> fp16   (M=16384, N=4096, K=1024)
    gemm_f16<1, 128><<<dim3(C4_ / 128, BT_ / 128), 256, SMEMB_128>>>(
        xnh, wcm, hh, BT_, C4_, C_, x1, cmk, nullptr);
    // 6. GEMM3 (MT=64 anti-tail): out = x1 + sigmoid(mix(xn2)) * (h @ W_cp)
    gemm_f16<2, 64><<<dim3(C_ / 128, BT_ / 64), 256, SMEMB_64>>>(
        hh, wcp, out, BT_, C_, C4_, x1, cmr, xnh);
}